// round 1
// baseline (speedup 1.0000x reference)
#include <cuda_runtime.h>
#include <math.h>

#define NTOT   16384
#define LATENT 20
#define UD     4
#define DH     80
#define TLEN   41
#define NSTEP  40
#define THREADS 128
#define BLOCKS  128

// scratch (no allocations allowed -> __device__ globals)
__device__ float g_u[NSTEP * UD];          // precomputed t-MLP outputs
__device__ float g_lq[(size_t)TLEN * NTOT]; // logqp trajectory (needed due to raw reshape)

// ---------------------------------------------------------------------------
// t-MLP: u_i = MLP(t_i), identical for all particles -> precompute 40x4 table
// ---------------------------------------------------------------------------
__global__ void tmlp_kernel(const float* __restrict__ t,
                            const float* __restrict__ tw_in, const float* __restrict__ tb_in,
                            const float* __restrict__ tw_h,  const float* __restrict__ tb_h,
                            const float* __restrict__ tw_out,const float* __restrict__ tb_out) {
    int i = threadIdx.x;
    if (i >= NSTEP) return;
    float ti = t[i];
    float h[20], h2[20];
#pragma unroll
    for (int j = 0; j < 20; j++) h[j] = fmaxf(tw_in[j] * ti + tb_in[j], 0.f);
    for (int l = 0; l < 4; l++) {
        const float* w = tw_h + l * 400;
        const float* b = tb_h + l * 20;
#pragma unroll
        for (int j = 0; j < 20; j++) {
            float a = b[j];
#pragma unroll
            for (int k = 0; k < 20; k++) a += w[j * 20 + k] * h[k];
            h2[j] = fmaxf(a, 0.f);
        }
#pragma unroll
        for (int j = 0; j < 20; j++) h[j] = h2[j];
    }
#pragma unroll
    for (int c = 0; c < 4; c++) {
        float a = tb_out[c];
#pragma unroll
        for (int k = 0; k < 20; k++) a += tw_out[c * 20 + k] * h[k];
        g_u[i * 4 + c] = a;
    }
}

// ---------------------------------------------------------------------------
// Main SDE integrator. 1 thread = 1 particle, full 40-step integration.
// Weights in smem (k-major for broadcast LDS.128), activations double-buffered
// in smem [80][128] (conflict-free: column = tid).
// ---------------------------------------------------------------------------
// smem float offsets
#define OFF_WIN  0                    // [24][80]
#define OFF_BIN  (OFF_WIN + 24*80)    // [80]
#define OFF_WH   (OFF_BIN + 80)       // [4][80k][80j]
#define OFF_BH   (OFF_WH + 4*6400)    // [4][80]
#define OFF_WOUT (OFF_BH + 320)       // [80k][20j]
#define OFF_BOUT (OFF_WOUT + 1600)    // [20]
#define OFF_HA   (OFF_BOUT + 20)      // [80][128]
#define OFF_HB   (OFF_HA + 80*128)    // [80][128]
#define SMEM_FLOATS (OFF_HB + 80*128) // 50020 floats = 200080 B

extern __shared__ float smem[];

__global__ void __launch_bounds__(THREADS, 1)
sde_kernel(const float* __restrict__ z, const float* __restrict__ t,
           const float* __restrict__ Tx, const float* __restrict__ noise,
           const float* __restrict__ dw_in, const float* __restrict__ db_in,
           const float* __restrict__ dw_h,  const float* __restrict__ db_h,
           const float* __restrict__ dw_out,const float* __restrict__ db_out,
           float* __restrict__ ys) {
    float* s_win  = smem + OFF_WIN;
    float* s_bin  = smem + OFF_BIN;
    float* s_wh   = smem + OFF_WH;
    float* s_bh   = smem + OFF_BH;
    float* s_wout = smem + OFF_WOUT;
    float* s_bout = smem + OFF_BOUT;
    float* s_hA   = smem + OFF_HA;
    float* s_hB   = smem + OFF_HB;

    const int tid = threadIdx.x;

    // cooperative load + transpose of weights into smem
    for (int idx = tid; idx < 24 * 80; idx += THREADS) {
        int j = idx / 24, k = idx % 24;
        s_win[k * 80 + j] = dw_in[idx];
    }
    for (int idx = tid; idx < 4 * 6400; idx += THREADS) {
        int l = idx / 6400, r = idx % 6400, j = r / 80, k = r % 80;
        s_wh[l * 6400 + k * 80 + j] = dw_h[idx];
    }
    for (int idx = tid; idx < 20 * 80; idx += THREADS) {
        int j = idx / 80, k = idx % 80;
        s_wout[k * 20 + j] = dw_out[idx];
    }
    for (int idx = tid; idx < 80;  idx += THREADS) s_bin[idx] = db_in[idx];
    for (int idx = tid; idx < 320; idx += THREADS) s_bh[idx]  = db_h[idx];
    if (tid < 20) s_bout[tid] = db_out[tid];
    __syncthreads();

    const int n = blockIdx.x * THREADS + tid;

    float y[20];
    const float* zp = z + (size_t)n * 20;
#pragma unroll
    for (int d = 0; d < 20; d++) y[d] = zp[d];
    const float Tval = Tx[n >> 6];
    float lq = 0.f;
    const float dt  = t[1] - t[0];
    const float sdt = sqrtf(dt);

    // t = 0 outputs
    {
        float* y0 = ys + (size_t)n * 20;
#pragma unroll
        for (int d = 0; d < 20; d++) y0[d] = y[d];
        g_lq[n] = 0.f;
    }

    for (int step = 0; step < NSTEP; step++) {
        const float ut0 = g_u[step * 4 + 0] * Tval;
        const float ut1 = g_u[step * 4 + 1] * Tval;
        const float ut2 = g_u[step * 4 + 2] * Tval;
        const float ut3 = g_u[step * 4 + 3] * Tval;

        // ---- input layer: x=[y(20), ut(4)] -> 80, relu ----
        for (int jt = 0; jt < 5; jt++) {
            float acc[16];
            const float* bb = s_bin + jt * 16;
#pragma unroll
            for (int j = 0; j < 16; j++) acc[j] = bb[j];
            const float* w = s_win + jt * 16;
#pragma unroll
            for (int k = 0; k < 20; k++) {
                float xv = y[k];
#pragma unroll
                for (int j = 0; j < 16; j++) acc[j] += w[k * 80 + j] * xv;
            }
#pragma unroll
            for (int j = 0; j < 16; j++) acc[j] += w[20 * 80 + j] * ut0;
#pragma unroll
            for (int j = 0; j < 16; j++) acc[j] += w[21 * 80 + j] * ut1;
#pragma unroll
            for (int j = 0; j < 16; j++) acc[j] += w[22 * 80 + j] * ut2;
#pragma unroll
            for (int j = 0; j < 16; j++) acc[j] += w[23 * 80 + j] * ut3;
            float* hw = s_hA + jt * 16 * 128 + tid;
#pragma unroll
            for (int j = 0; j < 16; j++) hw[j * 128] = fmaxf(acc[j], 0.f);
        }

        // ---- 4 hidden layers 80->80, tanh, ping-pong smem buffers ----
        float* hin  = s_hA;
        float* hout = s_hB;
        for (int l = 0; l < 4; l++) {
            const float* wl = s_wh + l * 6400;
            const float* bl = s_bh + l * 80;
            for (int jt = 0; jt < 5; jt++) {
                float acc[16];
                const float* bb = bl + jt * 16;
#pragma unroll
                for (int j = 0; j < 16; j++) acc[j] = bb[j];
                const float* w = wl + jt * 16;
#pragma unroll
                for (int k = 0; k < 80; k++) {
                    float hk = hin[k * 128 + tid];
#pragma unroll
                    for (int j = 0; j < 16; j++) acc[j] += w[k * 80 + j] * hk;
                }
                float* hw = hout + jt * 16 * 128 + tid;
#pragma unroll
                for (int j = 0; j < 16; j++) hw[j * 128] = tanhf(acc[j]);
            }
            float* tmp = hin; hin = hout; hout = tmp;
        }
        // after 4 swaps, final hidden is in hin (== s_hA)

        // ---- output layer 80 -> 20 ----
        float o[20];
#pragma unroll
        for (int j = 0; j < 20; j++) o[j] = s_bout[j];
#pragma unroll 4
        for (int k = 0; k < 80; k++) {
            float hk = hin[k * 128 + tid];
#pragma unroll
            for (int j = 0; j < 20; j++) o[j] += s_wout[k * 20 + j] * hk;
        }

        // ---- SDE update ----
        // h = theta*(mu - y) = -y ; f = o + y ; uu = 2*(o + 2y)
        // f_logqp = 0.5*sum(uu^2) = 2*sum((o+2y)^2)
        const float* np_ = noise + ((size_t)step * NTOT + n) * 22;
        float* yw = ys + ((size_t)(step + 1) * NTOT + n) * 20;
        float fq = 0.f;
#pragma unroll
        for (int d = 0; d < 20; d++) {
            float od = o[d];
            float f  = od + y[d];
            float uu = od + 2.f * y[d];
            fq += uu * uu;
            y[d] = y[d] + f * dt + 0.5f * np_[d] * sdt; // SIGMA = 0.5
            yw[d] = y[d];
        }
        lq += 2.f * fq * dt;
        g_lq[(size_t)(step + 1) * NTOT + n] = lq;
    }
}

// ---------------------------------------------------------------------------
// logqp gather: reference reshapes (41,16384,22) raw into (256,64,41,22) and
// takes [:, :, -1, -2]  ->  out[m] = lq_traj at chunk (41m+40)
// ---------------------------------------------------------------------------
__global__ void gather_kernel(float* __restrict__ out_lq) {
    int m = blockIdx.x * blockDim.x + threadIdx.x;
    if (m >= NTOT) return;
    int idx = 41 * m + 40;        // chunk index = t*16384 + n
    int tt = idx >> 14;           // / 16384
    int nn = idx & 16383;         // % 16384
    out_lq[m] = g_lq[(size_t)tt * NTOT + nn];
}

// ---------------------------------------------------------------------------
extern "C" void kernel_launch(void* const* d_in, const int* in_sizes, int n_in,
                              void* d_out, int out_size) {
    const float* z      = (const float*)d_in[0];
    const float* t      = (const float*)d_in[1];
    const float* Tx     = (const float*)d_in[2];
    const float* noise  = (const float*)d_in[3];
    const float* tw_in  = (const float*)d_in[4];
    const float* tb_in  = (const float*)d_in[5];
    const float* tw_h   = (const float*)d_in[6];
    const float* tb_h   = (const float*)d_in[7];
    const float* tw_out = (const float*)d_in[8];
    const float* tb_out = (const float*)d_in[9];
    const float* dw_in  = (const float*)d_in[10];
    const float* db_in  = (const float*)d_in[11];
    const float* dw_h   = (const float*)d_in[12];
    const float* db_h   = (const float*)d_in[13];
    const float* dw_out = (const float*)d_in[14];
    const float* db_out = (const float*)d_in[15];

    float* ys    = (float*)d_out;
    float* lqout = ys + (size_t)TLEN * NTOT * LATENT;

    const size_t smem_bytes = (size_t)SMEM_FLOATS * sizeof(float); // ~200 KB
    cudaFuncSetAttribute(sde_kernel, cudaFuncAttributeMaxDynamicSharedMemorySize,
                         (int)smem_bytes);

    tmlp_kernel<<<1, 64>>>(t, tw_in, tb_in, tw_h, tb_h, tw_out, tb_out);
    sde_kernel<<<BLOCKS, THREADS, smem_bytes>>>(z, t, Tx, noise,
                                                dw_in, db_in, dw_h, db_h,
                                                dw_out, db_out, ys);
    gather_kernel<<<NTOT / 256, 256>>>(lqout);
}

// round 2
// speedup vs baseline: 1.2233x; 1.2233x over previous
#include <cuda_runtime.h>
#include <math.h>

#define NTOT    16384
#define TLEN    41
#define NSTEP   40
#define THREADS 128
#define BLOCKS  128

// ---- smem float offsets (weights k-major: adjacent j contiguous) ----
#define OFF_WIN  0                      // [24k][80j]
#define OFF_BIN  (OFF_WIN + 24*80)      // [80]
#define OFF_WH   (OFF_BIN + 80)         // [4l][80k][80j]
#define OFF_BH   (OFF_WH + 4*6400)      // [4][80]
#define OFF_WOUT (OFF_BH + 320)         // [80k][20j]
#define OFF_BOUT (OFF_WOUT + 1600)      // [20]
#define OFF_U    (OFF_BOUT + 20)        // [40][4] t-MLP table
#define OFF_HA   (OFF_U + 160)          // [80][128]
#define OFF_HB   (OFF_HA + 80*128)      // [80][128]
#define SMEM_FLOATS (OFF_HB + 80*128)   // 50180 floats = 200720 B

typedef unsigned long long u64;

// packed f32x2 FMA (sm_100+): d = a*b + c per 32-bit lane
#define FMA2(d, a, b, c) \
    asm("fma.rn.f32x2 %0, %1, %2, %3;" : "=l"(d) : "l"(a), "l"(b), "l"(c))
#define PACK2(d, f) do { unsigned int _u = __float_as_uint(f); \
    asm("mov.b64 %0, {%1, %2};" : "=l"(d) : "r"(_u), "r"(_u)); } while (0)
#define UNPACK2(lo, hi, s) do { unsigned int _a, _b; \
    asm("mov.b64 {%0, %1}, %2;" : "=r"(_a), "=r"(_b) : "l"(s)); \
    lo = __uint_as_float(_a); hi = __uint_as_float(_b); } while (0)
#define TANHA(d, x) asm("tanh.approx.f32 %0, %1;" : "=f"(d) : "f"(x))

extern __shared__ float smem[];

__global__ void __launch_bounds__(THREADS, 1)
sde_kernel(const float* __restrict__ z, const float* __restrict__ t,
           const float* __restrict__ Tx, const float* __restrict__ noise,
           const float* __restrict__ tw_in, const float* __restrict__ tb_in,
           const float* __restrict__ tw_h,  const float* __restrict__ tb_h,
           const float* __restrict__ tw_out,const float* __restrict__ tb_out,
           const float* __restrict__ dw_in, const float* __restrict__ db_in,
           const float* __restrict__ dw_h,  const float* __restrict__ db_h,
           const float* __restrict__ dw_out,const float* __restrict__ db_out,
           float* __restrict__ ys, float* __restrict__ lqout) {
    float* s_win  = smem + OFF_WIN;
    float* s_bin  = smem + OFF_BIN;
    float* s_wh   = smem + OFF_WH;
    float* s_bh   = smem + OFF_BH;
    float* s_wout = smem + OFF_WOUT;
    float* s_bout = smem + OFF_BOUT;
    float* s_u    = smem + OFF_U;
    float* s_hA   = smem + OFF_HA;
    float* s_hB   = smem + OFF_HB;

    const int tid = threadIdx.x;

    // ---- cooperative load + transpose of drift weights into smem ----
    for (int idx = tid; idx < 24 * 80; idx += THREADS) {
        int j = idx / 24, k = idx % 24;
        s_win[k * 80 + j] = dw_in[idx];
    }
    for (int idx = tid; idx < 4 * 6400; idx += THREADS) {
        int l = idx / 6400, r = idx % 6400, j = r / 80, k = r % 80;
        s_wh[l * 6400 + k * 80 + j] = dw_h[idx];
    }
    for (int idx = tid; idx < 20 * 80; idx += THREADS) {
        int j = idx / 80, k = idx % 80;
        s_wout[k * 20 + j] = dw_out[idx];
    }
    for (int idx = tid; idx < 80;  idx += THREADS) s_bin[idx] = db_in[idx];
    for (int idx = tid; idx < 320; idx += THREADS) s_bh[idx]  = db_h[idx];
    if (tid < 20) s_bout[tid] = db_out[tid];

    // ---- t-MLP fused: thread i (<40) computes u(t_i) -> s_u ----
    if (tid < NSTEP) {
        float ti = t[tid];
        float h[20], h2[20];
#pragma unroll
        for (int j = 0; j < 20; j++) h[j] = fmaxf(tw_in[j] * ti + tb_in[j], 0.f);
        for (int l = 0; l < 4; l++) {
            const float* w = tw_h + l * 400;
            const float* b = tb_h + l * 20;
#pragma unroll
            for (int j = 0; j < 20; j++) {
                float a = b[j];
#pragma unroll
                for (int k = 0; k < 20; k++) a += w[j * 20 + k] * h[k];
                h2[j] = fmaxf(a, 0.f);
            }
#pragma unroll
            for (int j = 0; j < 20; j++) h[j] = h2[j];
        }
#pragma unroll
        for (int c = 0; c < 4; c++) {
            float a = tb_out[c];
#pragma unroll
            for (int k = 0; k < 20; k++) a += tw_out[c * 20 + k] * h[k];
            s_u[tid * 4 + c] = a;
        }
    }
    __syncthreads();

    const int n = blockIdx.x * THREADS + tid;

    // ---- particle state ----
    float y[20];
    {
        const float4* zp = (const float4*)(z + (size_t)n * 20);
#pragma unroll
        for (int i = 0; i < 5; i++) {
            float4 v = zp[i];
            y[4*i+0] = v.x; y[4*i+1] = v.y; y[4*i+2] = v.z; y[4*i+3] = v.w;
        }
    }
    const float Tval = Tx[n >> 6];
    float lq = 0.f;
    const float dt  = t[1] - t[0];
    const float sdt = sqrtf(dt);

    // t = 0 outputs (ys slice + logqp hits in the t=0 chunk range)
    {
        float4* y0 = (float4*)(ys + (size_t)n * 20);
#pragma unroll
        for (int i = 0; i < 5; i++)
            y0[i] = make_float4(y[4*i], y[4*i+1], y[4*i+2], y[4*i+3]);
        if (n >= 40 && (n - 40) % 41 == 0) lqout[(n - 40) / 41] = 0.f;
    }

    for (int step = 0; step < NSTEP; step++) {
        const float ut0 = s_u[step * 4 + 0] * Tval;
        const float ut1 = s_u[step * 4 + 1] * Tval;
        const float ut2 = s_u[step * 4 + 2] * Tval;
        const float ut3 = s_u[step * 4 + 3] * Tval;

        // ======== input layer: [y(20), ut(4)] -> 80, relu ========
        {
            float xin[24];
#pragma unroll
            for (int d = 0; d < 20; d++) xin[d] = y[d];
            xin[20] = ut0; xin[21] = ut1; xin[22] = ut2; xin[23] = ut3;

            u64 acc[40];
            const u64* bv = (const u64*)s_bin;
#pragma unroll
            for (int j2 = 0; j2 < 40; j2++) acc[j2] = bv[j2];
#pragma unroll
            for (int k = 0; k < 24; k++) {
                u64 x2; PACK2(x2, xin[k]);
                const ulonglong2* w = (const ulonglong2*)(s_win + k * 80);
#pragma unroll
                for (int q = 0; q < 20; q++) {
                    ulonglong2 wv = w[q];
                    FMA2(acc[2*q],   wv.x, x2, acc[2*q]);
                    FMA2(acc[2*q+1], wv.y, x2, acc[2*q+1]);
                }
            }
#pragma unroll
            for (int j2 = 0; j2 < 40; j2++) {
                float a, b; UNPACK2(a, b, acc[j2]);
                s_hA[(2*j2)   * 128 + tid] = fmaxf(a, 0.f);
                s_hA[(2*j2+1) * 128 + tid] = fmaxf(b, 0.f);
            }
        }

        // ======== 4 hidden layers 80 -> 80, tanh.approx ========
        float* hin  = s_hA;
        float* hout = s_hB;
        for (int l = 0; l < 4; l++) {
            const float* wl = s_wh + l * 6400;
            u64 acc[40];
            const u64* bv = (const u64*)(s_bh + l * 80);
#pragma unroll
            for (int j2 = 0; j2 < 40; j2++) acc[j2] = bv[j2];
#pragma unroll 8
            for (int k = 0; k < 80; k++) {
                float hk = hin[k * 128 + tid];
                u64 h2; PACK2(h2, hk);
                const ulonglong2* w = (const ulonglong2*)(wl + k * 80);
#pragma unroll
                for (int q = 0; q < 20; q++) {
                    ulonglong2 wv = w[q];
                    FMA2(acc[2*q],   wv.x, h2, acc[2*q]);
                    FMA2(acc[2*q+1], wv.y, h2, acc[2*q+1]);
                }
            }
#pragma unroll
            for (int j2 = 0; j2 < 40; j2++) {
                float a, b; UNPACK2(a, b, acc[j2]);
                TANHA(a, a); TANHA(b, b);
                hout[(2*j2)   * 128 + tid] = a;
                hout[(2*j2+1) * 128 + tid] = b;
            }
            float* tmp = hin; hin = hout; hout = tmp;
        }
        // final hidden is in hin (== s_hA after 4 swaps)

        // ---- prefetch noise (DRAM latency hidden under output layer) ----
        float nz[20];
        {
            const float2* np2 = (const float2*)(noise + ((size_t)step * NTOT + n) * 22);
#pragma unroll
            for (int i = 0; i < 10; i++) {
                float2 v = np2[i];
                nz[2*i] = v.x; nz[2*i+1] = v.y;
            }
        }

        // ======== output layer 80 -> 20 ========
        float o[20];
        {
            u64 oc[10];
            const u64* bv = (const u64*)s_bout;
#pragma unroll
            for (int q = 0; q < 10; q++) oc[q] = bv[q];
#pragma unroll 8
            for (int k = 0; k < 80; k++) {
                float hk = hin[k * 128 + tid];
                u64 h2; PACK2(h2, hk);
                const ulonglong2* w = (const ulonglong2*)(s_wout + k * 20);
#pragma unroll
                for (int q = 0; q < 5; q++) {
                    ulonglong2 wv = w[q];
                    FMA2(oc[2*q],   wv.x, h2, oc[2*q]);
                    FMA2(oc[2*q+1], wv.y, h2, oc[2*q+1]);
                }
            }
#pragma unroll
            for (int q = 0; q < 10; q++) UNPACK2(o[2*q], o[2*q+1], oc[q]);
        }

        // ======== SDE update ========
        // h = theta*(mu - y) = -y ; f = o + y ; uu = 2*(o + 2y)
        // f_logqp = 0.5*sum(uu^2) = 2*sum((o+2y)^2)
        float fq = 0.f;
#pragma unroll
        for (int d = 0; d < 20; d++) {
            float od = o[d];
            float f  = od + y[d];
            float uu = od + 2.f * y[d];
            fq += uu * uu;
            y[d] = y[d] + f * dt + 0.5f * nz[d] * sdt;   // SIGMA = 0.5
        }
        {
            float4* yw = (float4*)(ys + ((size_t)(step + 1) * NTOT + n) * 20);
#pragma unroll
            for (int i = 0; i < 5; i++)
                yw[i] = make_float4(y[4*i], y[4*i+1], y[4*i+2], y[4*i+3]);
        }
        lq += 2.f * fq * dt;
        {
            // logqp output: out[m] = lq trajectory at flat chunk 41m+40
            size_t idx = (size_t)(step + 1) * NTOT + n;
            size_t r = idx - 40;
            if (r % 41 == 0) lqout[r / 41] = lq;
        }
    }
}

// ---------------------------------------------------------------------------
extern "C" void kernel_launch(void* const* d_in, const int* in_sizes, int n_in,
                              void* d_out, int out_size) {
    const float* z      = (const float*)d_in[0];
    const float* t      = (const float*)d_in[1];
    const float* Tx     = (const float*)d_in[2];
    const float* noise  = (const float*)d_in[3];
    const float* tw_in  = (const float*)d_in[4];
    const float* tb_in  = (const float*)d_in[5];
    const float* tw_h   = (const float*)d_in[6];
    const float* tb_h   = (const float*)d_in[7];
    const float* tw_out = (const float*)d_in[8];
    const float* tb_out = (const float*)d_in[9];
    const float* dw_in  = (const float*)d_in[10];
    const float* db_in  = (const float*)d_in[11];
    const float* dw_h   = (const float*)d_in[12];
    const float* db_h   = (const float*)d_in[13];
    const float* dw_out = (const float*)d_in[14];
    const float* db_out = (const float*)d_in[15];

    float* ys    = (float*)d_out;
    float* lqout = ys + (size_t)TLEN * NTOT * 20;

    const size_t smem_bytes = (size_t)SMEM_FLOATS * sizeof(float); // ~200 KB
    cudaFuncSetAttribute(sde_kernel, cudaFuncAttributeMaxDynamicSharedMemorySize,
                         (int)smem_bytes);

    sde_kernel<<<BLOCKS, THREADS, smem_bytes>>>(z, t, Tx, noise,
                                                tw_in, tb_in, tw_h, tb_h,
                                                tw_out, tb_out,
                                                dw_in, db_in, dw_h, db_h,
                                                dw_out, db_out, ys, lqout);
}